// round 15
// baseline (speedup 1.0000x reference)
#include <cuda_runtime.h>
#include <cuda_fp16.h>
#include <math.h>
#include <cstdint>

#define NB 64
#define NL 64
#define ND 512

// ---------------- device scratch ----------------
__device__ float g_G[NB * NL * NL];
__device__ float g_w1[NB * NL];
__device__ float g_sim[NB * NB];
__device__ float g_S[4096u * 4096u];

// ---------------- helpers ----------------
__device__ __forceinline__ uint32_t smem_u32(const void* p) {
    uint32_t a;
    asm("{ .reg .u64 t; cvta.to.shared.u64 t, %1; cvt.u32.u64 %0, t; }" : "=r"(a) : "l"(p));
    return a;
}
__device__ __forceinline__ void lds64nv(uint32_t& x, uint32_t& y, uint32_t a) {
    asm("ld.shared.v2.b32 {%0, %1}, [%2];" : "=r"(x), "=r"(y) : "r"(a));
}
__device__ __forceinline__ void lds64(uint32_t& x, uint32_t& y, uint32_t a) {
    asm volatile("ld.shared.v2.b32 {%0, %1}, [%2];" : "=r"(x), "=r"(y) : "r"(a));
}
__device__ __forceinline__ void sts128v(uint32_t a, uint32_t x, uint32_t y, uint32_t z, uint32_t w) {
    asm volatile("st.shared.v4.b32 [%0], {%1, %2, %3, %4};"
                 :: "r"(a), "r"(x), "r"(y), "r"(z), "r"(w) : "memory");
}
__device__ __forceinline__ uint32_t pkh(__half a, __half b) {
    __half2 h = __halves2half2(a, b);
    return *reinterpret_cast<uint32_t*>(&h);
}
__device__ __forceinline__ void mma_f16(float* c, const uint32_t* a, const uint32_t* b) {
    asm volatile(
        "mma.sync.aligned.m16n8k16.row.col.f32.f16.f16.f32 "
        "{%0,%1,%2,%3}, {%4,%5,%6,%7}, {%8,%9}, {%0,%1,%2,%3};"
        : "+f"(c[0]), "+f"(c[1]), "+f"(c[2]), "+f"(c[3])
        : "r"(a[0]), "r"(a[1]), "r"(a[2]), "r"(a[3]), "r"(b[0]), "r"(b[1]));
}

// FMA-pipe exp for x <= 0 (clamped at -87), rel err ~1e-7.
__device__ __forceinline__ float fexp(float x) {
    x = fmaxf(x, -87.0f);
    float t = fmaf(x, 1.4426950408889634f, 12582912.0f);
    float n = t - 12582912.0f;
    float f = fmaf(x, 1.4426950408889634f, -n);
    float p = 1.33978935e-3f;
    p = fmaf(p, f, 9.67518295e-3f);
    p = fmaf(p, f, 5.55041086e-2f);
    p = fmaf(p, f, 2.40226507e-1f);
    p = fmaf(p, f, 6.93147182e-1f);
    p = fmaf(p, f, 1.0f);
    int ni = __float_as_int(t) - 0x4B400000;
    float s = __int_as_float((ni + 127) << 23);
    return p * s;
}

// ===========================================================================
// Kernel A: S-GEMM (8 warps, warp tile 64x32) with anti-phase warp scheduling:
// even warps MMA->STS, odd warps STS->MMA, so smem port and tensor pipe
// overlap across warp halves instead of serializing in lockstep.
// ===========================================================================
#define BK 32
#define NCH (ND / BK)
#define ROWW 24u
#define OFF_AHI 0u
#define OFF_ALO 12288u
#define OFF_BHI 24576u
#define OFF_BLO 36864u
#define STAGE_B 49152u
#define SMEM_TOTAL (2u * STAGE_B)

__global__ __launch_bounds__(256, 1) void s_gemm_kernel(const float* __restrict__ ecg,
                                                        const float* __restrict__ sent) {
    extern __shared__ char dsm[];
    const uint32_t sbase = smem_u32(dsm);

    const int tid = threadIdx.x;
    const int wid = tid >> 5, lane = tid & 31;
    const int tileN = blockIdx.x;
    const int tileM = blockIdx.y;

    const int grow = tid >> 1;
    const int g = tid & 1;
    const float* Ag = sent + ((size_t)tileM * 128 + grow) * ND + g * 16;
    const float* Bg = ecg + ((size_t)tileN * 128 + grow) * ND + g * 16;
    const uint32_t wbB = ((uint32_t)grow * ROWW + (uint32_t)g * 12u) * 4u;

    const uint32_t warpM = (uint32_t)(wid & 1) * 64u;
    const uint32_t warpN = (uint32_t)(wid >> 1) * 32u;
    const uint32_t lg = lane >> 2, lt = lane & 3;

    float acc[4][4][4];
#pragma unroll
    for (int mi = 0; mi < 4; ++mi)
#pragma unroll
        for (int ni = 0; ni < 4; ++ni)
#pragma unroll
            for (int r = 0; r < 4; ++r) acc[mi][ni][r] = 0.f;

    float4 ra[4], rb[4];
    auto ldg_chunk = [&](int t) {
#pragma unroll
        for (int r = 0; r < 4; ++r) {
            ra[r] = *reinterpret_cast<const float4*>(Ag + t * BK + r * 4);
            rb[r] = *reinterpret_cast<const float4*>(Bg + t * BK + r * 4);
        }
    };

    auto cvt_store = [&](const float4* q, uint32_t hiB, uint32_t loB) {
        float v[16];
#pragma unroll
        for (int r = 0; r < 4; ++r) {
            v[r * 4 + 0] = q[r].x; v[r * 4 + 1] = q[r].y;
            v[r * 4 + 2] = q[r].z; v[r * 4 + 3] = q[r].w;
        }
        __half H[16], L[16];
#pragma unroll
        for (int idx = 0; idx < 16; ++idx) {
            __half h = __float2half_rn(v[idx]);
            H[idx] = h;
            L[idx] = __float2half_rn(v[idx] - __half2float(h));
        }
        uint32_t W0 = pkh(H[0], H[1]), W1 = pkh(H[8], H[9]);
        uint32_t W2 = pkh(H[2], H[3]), W3 = pkh(H[10], H[11]);
        uint32_t W4 = pkh(H[4], H[5]), W5 = pkh(H[12], H[13]);
        uint32_t W6 = pkh(H[6], H[7]), W7 = pkh(H[14], H[15]);
        sts128v(hiB + wbB, W0, W1, W2, W3);
        sts128v(hiB + wbB + 16u, W4, W5, W6, W7);
        uint32_t X0 = pkh(L[0], L[1]), X1 = pkh(L[8], L[9]);
        uint32_t X2 = pkh(L[2], L[3]), X3 = pkh(L[10], L[11]);
        uint32_t X4 = pkh(L[4], L[5]), X5 = pkh(L[12], L[13]);
        uint32_t X6 = pkh(L[6], L[7]), X7 = pkh(L[14], L[15]);
        sts128v(loB + wbB, X0, X1, X2, X3);
        sts128v(loB + wbB + 16u, X4, X5, X6, X7);
    };

    auto sts_chunk = [&](uint32_t st) {
        cvt_store(ra, st + OFF_AHI, st + OFF_ALO);
        cvt_store(rb, st + OFF_BHI, st + OFF_BLO);
    };

    // one k16-step worth of fragment loads + MMAs from buffer st
    auto mma_step = [&](uint32_t st, int s) {
        uint32_t ah[4][4], al[4][4], bh[4][2], bl[4][2];
        const uint32_t kw = (uint32_t)s * 12u + 2u * lt;
#pragma unroll
        for (int mi = 0; mi < 4; ++mi) {
            uint32_t r0 = (warpM + mi * 16u + lg) * ROWW + kw;
            uint32_t r1 = r0 + 8u * ROWW;
            lds64nv(ah[mi][0], ah[mi][2], st + OFF_AHI + r0 * 4u);
            lds64nv(ah[mi][1], ah[mi][3], st + OFF_AHI + r1 * 4u);
            lds64nv(al[mi][0], al[mi][2], st + OFF_ALO + r0 * 4u);
            lds64nv(al[mi][1], al[mi][3], st + OFF_ALO + r1 * 4u);
        }
#pragma unroll
        for (int ni = 0; ni < 4; ++ni) {
            uint32_t r0 = (warpN + ni * 8u + lg) * ROWW + kw;
            lds64nv(bh[ni][0], bh[ni][1], st + OFF_BHI + r0 * 4u);
            lds64nv(bl[ni][0], bl[ni][1], st + OFF_BLO + r0 * 4u);
        }
#pragma unroll
        for (int mi = 0; mi < 4; ++mi)
#pragma unroll
            for (int ni = 0; ni < 4; ++ni) {
                mma_f16(acc[mi][ni], ah[mi], bh[ni]);
                mma_f16(acc[mi][ni], ah[mi], bl[ni]);
                mma_f16(acc[mi][ni], al[mi], bh[ni]);
            }
    };

    ldg_chunk(0);
    sts_chunk(sbase);
    ldg_chunk(1);
    __syncthreads();

    const bool oddw = (wid & 1) != 0;
    for (int t = 0; t < NCH; ++t) {
        const uint32_t st = sbase + (uint32_t)(t & 1) * STAGE_B;
        const uint32_t stn = sbase + (uint32_t)((t + 1) & 1) * STAGE_B;
        const bool haveNext = (t + 1 < NCH);

        if (oddw) {
            // odd warps: stage first (port), then MMA s=1, s=0 (tensor)
            if (haveNext) sts_chunk(stn);
            mma_step(st, 1);
            mma_step(st, 0);
        } else {
            // even warps: MMA s=0, s=1 first (tensor), then stage (port)
            mma_step(st, 0);
            mma_step(st, 1);
            if (haveNext) sts_chunk(stn);
        }
        if (t + 2 < NCH) ldg_chunk(t + 2);
        __syncthreads();
    }

    const size_t rbase = (size_t)tileM * 128 + warpM + lg;
    const size_t cbase = (size_t)tileN * 128 + warpN + lt * 2;
#pragma unroll
    for (int mi = 0; mi < 4; ++mi)
#pragma unroll
        for (int ni = 0; ni < 4; ++ni) {
            float* p0 = g_S + (rbase + mi * 16) * 4096u + cbase + ni * 8;
            *reinterpret_cast<float2*>(p0) = make_float2(acc[mi][ni][0], acc[mi][ni][1]);
            *reinterpret_cast<float2*>(p0 + 8 * 4096u) = make_float2(acc[mi][ni][2], acc[mi][ni][3]);
        }
}

// ===========================================================================
// Kernel B: Gram quadrants (256 CTAs) + w1 norms. (R10)
// ===========================================================================
__global__ __launch_bounds__(256) void gram_kernel(const float* __restrict__ ecg,
                                                   const float* __restrict__ sent) {
    __shared__ float sA[32 * 66];
    __shared__ float sB[32 * 66];
    const int j = blockIdx.x >> 2;
    const int quad = blockIdx.x & 3;
    const int qr = (quad >> 1) * 32, qc = (quad & 1) * 32;
    const int tid = threadIdx.x;
    const int tx = tid & 15, ty = tid >> 4;
    const int r0 = ty * 2, c0 = tx * 2;
    const float* base = ecg + (size_t)j * NL * ND;

    float c00 = 0.f, c01 = 0.f, c10 = 0.f, c11 = 0.f;
    const int lrow = tid >> 3;
    const int lcol = (tid & 7) * 8;

    for (int kt = 0; kt < ND; kt += 64) {
        __syncthreads();
#pragma unroll
        for (int r = 0; r < 2; ++r) {
            float4 va = *reinterpret_cast<const float4*>(base + (qr + lrow) * ND + kt + lcol + r * 4);
            sA[lrow * 66 + lcol + r * 4 + 0] = va.x;
            sA[lrow * 66 + lcol + r * 4 + 1] = va.y;
            sA[lrow * 66 + lcol + r * 4 + 2] = va.z;
            sA[lrow * 66 + lcol + r * 4 + 3] = va.w;
            float4 vb = *reinterpret_cast<const float4*>(base + (qc + lrow) * ND + kt + lcol + r * 4);
            sB[lrow * 66 + lcol + r * 4 + 0] = vb.x;
            sB[lrow * 66 + lcol + r * 4 + 1] = vb.y;
            sB[lrow * 66 + lcol + r * 4 + 2] = vb.z;
            sB[lrow * 66 + lcol + r * 4 + 3] = vb.w;
        }
        __syncthreads();
#pragma unroll 8
        for (int k = 0; k < 64; ++k) {
            float a0 = sA[r0 * 66 + k], a1 = sA[(r0 + 1) * 66 + k];
            float b0 = sB[c0 * 66 + k], b1 = sB[(c0 + 1) * 66 + k];
            c00 = fmaf(a0, b0, c00);
            c01 = fmaf(a0, b1, c01);
            c10 = fmaf(a1, b0, c10);
            c11 = fmaf(a1, b1, c11);
        }
    }
    float* Gp = g_G + (size_t)j * NL * NL;
    Gp[(qr + r0) * NL + qc + c0] = c00;
    Gp[(qr + r0) * NL + qc + c0 + 1] = c01;
    Gp[(qr + r0 + 1) * NL + qc + c0] = c10;
    Gp[(qr + r0 + 1) * NL + qc + c0 + 1] = c11;

    if (quad == 0) {
        int q = tid >> 2;
        int p = tid & 3;
        const float* sp = sent + (size_t)j * NL * ND + q * ND + p * 128;
        float s = 0.f;
#pragma unroll 8
        for (int t2 = 0; t2 < 32; t2++) {
            float4 v = *reinterpret_cast<const float4*>(sp + t2 * 4);
            s = fmaf(v.x, v.x, fmaf(v.y, v.y, fmaf(v.z, v.z, fmaf(v.w, v.w, s))));
        }
        s += __shfl_xor_sync(0xffffffffu, s, 1);
        s += __shfl_xor_sync(0xffffffffu, s, 2);
        if (p == 0) g_w1[j * NL + q] = sqrtf(s);
    }
}

// ===========================================================================
// Kernel C: pair epilogue (R10 body, unchanged)
// ===========================================================================
#define P_AH 0
#define P_A2H 4352
#define P_A2L 6656
#define P_GBH 8960
#define P_GBL 11264
#define P_PB 13568
#define P_CM 14656
#define P_CZ 14720
#define P_ES 14784
#define PAIR_SMEM (14848 * 4)

__global__ __launch_bounds__(256) void pair_kernel(float* __restrict__ out) {
    extern __shared__ float shf[];
    uint32_t* shw = reinterpret_cast<uint32_t*>(shf);
    const unsigned FULL = 0xffffffffu;

    const int i = blockIdx.x, j = blockIdx.y;
    const int tid = threadIdx.x;
    const int wid = tid >> 5, lane = tid & 31;
    const int tx = tid & 15, ty = tid >> 4;
    const int row0 = ty * 4, col0 = tx * 4;

    const int gg8 = (col0 >> 4) * 8;
    const int pp = col0 & 15;
    const int wsel = (pp < 8) ? pp : pp - 7;

    float c[4][4];
    const float* Sp = g_S + ((size_t)i * 64) * 4096u + (size_t)j * 64;
#pragma unroll
    for (int m = 0; m < 4; m++) {
        float4 v4 = *reinterpret_cast<const float4*>(Sp + (size_t)(row0 + m) * 4096u + col0);
        c[m][0] = v4.x; c[m][1] = v4.y; c[m][2] = v4.z; c[m][3] = v4.w;
    }

    {
        const float* Gp = g_G + (size_t)j * NL * NL;
        const int f = tx * 4;
        const int fg8 = (f >> 4) * 8;
        const int fp = f & 15;
        const int fw = (fp < 8) ? fp : fp - 7;
#pragma unroll
        for (int r = 0; r < 4; ++r) {
            int q = ty + r * 16;
            float4 gq = *reinterpret_cast<const float4*>(Gp + q * NL + f);
            __half h0 = __float2half_rn(gq.x), h1 = __float2half_rn(gq.y);
            __half h2 = __float2half_rn(gq.z), h3 = __float2half_rn(gq.w);
            __half l0 = __float2half_rn(gq.x - __half2float(h0));
            __half l1 = __float2half_rn(gq.y - __half2float(h1));
            __half l2 = __float2half_rn(gq.z - __half2float(h2));
            __half l3 = __float2half_rn(gq.w - __half2float(h3));
            int wb = q * 36 + fg8 + fw;
            shw[P_GBH + wb] = pkh(h0, h1);
            shw[P_GBH + wb + 2] = pkh(h2, h3);
            shw[P_GBL + wb] = pkh(l0, l1);
            shw[P_GBL + wb + 2] = pkh(l2, l3);
        }
    }

    // ---- col max ----
    {
        float pm[4];
#pragma unroll
        for (int n = 0; n < 4; n++) {
            pm[n] = c[0][n];
#pragma unroll
            for (int m = 1; m < 4; m++) pm[n] = fmaxf(pm[n], c[m][n]);
            pm[n] = fmaxf(pm[n], __shfl_xor_sync(FULL, pm[n], 16));
        }
        if (lane < 16) {
#pragma unroll
            for (int n = 0; n < 4; n++) shf[P_PB + wid * 68 + col0 + n] = pm[n];
        }
    }
    __syncthreads();
    if (tid < 64) {
        float m = -1e30f;
#pragma unroll
        for (int p = 0; p < 8; p++) m = fmaxf(m, shf[P_PB + p * 68 + tid]);
        shf[P_CM + tid] = m;
    }
    __syncthreads();

    // ---- e1 once; col sums ----
    float v[4][4];
    {
        float ps[4];
#pragma unroll
        for (int n = 0; n < 4; n++) {
            float cm = shf[P_CM + col0 + n];
            float s = 0.f;
#pragma unroll
            for (int m = 0; m < 4; m++) {
                float e = fexp(c[m][n] - cm);
                v[m][n] = e;
                s += e;
            }
            ps[n] = s + __shfl_xor_sync(FULL, s, 16);
        }
        if (lane < 16) {
#pragma unroll
            for (int n = 0; n < 4; n++) shf[P_PB + wid * 68 + col0 + n] = ps[n];
        }
    }
    __syncthreads();
    if (tid < 64) {
        float z = 0.f;
#pragma unroll
        for (int p = 0; p < 8; p++) z += shf[P_PB + p * 68 + tid];
        shf[P_CZ + tid] = 4.f / z;
    }
    __syncthreads();

#pragma unroll
    for (int n = 0; n < 4; n++) {
        float zr = shf[P_CZ + col0 + n];
#pragma unroll
        for (int m = 0; m < 4; m++) v[m][n] *= zr;
    }

    float rm[4];
#pragma unroll
    for (int m = 0; m < 4; m++) {
        float pm = v[m][0];
#pragma unroll
        for (int n = 1; n < 4; n++) pm = fmaxf(pm, v[m][n]);
#pragma unroll
        for (int off = 1; off < 16; off <<= 1)
            pm = fmaxf(pm, __shfl_xor_sync(FULL, pm, off));
        rm[m] = pm;
    }

    float rz[4];
#pragma unroll
    for (int m = 0; m < 4; m++) {
        float s = 0.f;
#pragma unroll
        for (int n = 0; n < 4; n++) {
            float e = fexp(v[m][n] - rm[m]);
            v[m][n] = e;
            s += e;
        }
#pragma unroll
        for (int off = 1; off < 16; off <<= 1)
            s += __shfl_xor_sync(FULL, s, off);
        rz[m] = 1.f / s;
    }

#pragma unroll
    for (int m = 0; m < 4; m++) {
        float w12p = 0.f;
        float a2v[4];
#pragma unroll
        for (int n = 0; n < 4; n++) {
            float a2 = v[m][n] * rz[m];
            a2v[n] = a2;
            v[m][n] = a2;
            w12p = fmaf(a2, c[m][n], w12p);
            shf[P_AH + (row0 + m) * 68 + col0 + n] = a2;
        }
#pragma unroll
        for (int off = 1; off < 16; off <<= 1)
            w12p += __shfl_xor_sync(FULL, w12p, off);
        if (tx == 0) shf[P_CM + row0 + m] = w12p;
        __half h0 = __float2half_rn(a2v[0]), h1 = __float2half_rn(a2v[1]);
        __half h2 = __float2half_rn(a2v[2]), h3 = __float2half_rn(a2v[3]);
        __half l0 = __float2half_rn(a2v[0] - __half2float(h0));
        __half l1 = __float2half_rn(a2v[1] - __half2float(h1));
        __half l2 = __float2half_rn(a2v[2] - __half2float(h2));
        __half l3 = __float2half_rn(a2v[3] - __half2float(h3));
        int wb = (row0 + m) * 36 + gg8 + wsel;
        shw[P_A2H + wb] = pkh(h0, h1);
        shw[P_A2H + wb + 2] = pkh(h2, h3);
        shw[P_A2L + wb] = pkh(l0, l1);
        shw[P_A2L + wb + 2] = pkh(l2, l3);
    }
    __syncthreads();

    // ---- GEMM2 on tensor ----
    const uint32_t warpM2 = (uint32_t)(wid & 1) * 32u;
    const uint32_t warpN2 = (uint32_t)(wid >> 1) * 16u;
    const uint32_t lg = lane >> 2, lt = lane & 3;
    const uint32_t a2hB = smem_u32(shw + P_A2H);
    const uint32_t a2lB = smem_u32(shw + P_A2L);
    const uint32_t gbhB = smem_u32(shw + P_GBH);
    const uint32_t gblB = smem_u32(shw + P_GBL);

    float t4[2][2][4];
#pragma unroll
    for (int mi = 0; mi < 2; ++mi)
#pragma unroll
        for (int ni = 0; ni < 2; ++ni)
#pragma unroll
            for (int r = 0; r < 4; ++r) t4[mi][ni][r] = 0.f;

#pragma unroll
    for (int kk = 0; kk < 4; ++kk) {
        const uint32_t kw = (uint32_t)kk * 8u + 2u * lt;
        uint32_t bh[2][2], bl[2][2];
#pragma unroll
        for (int ni = 0; ni < 2; ++ni) {
            uint32_t r0 = (warpN2 + ni * 8u + lg) * 36u + kw;
            lds64(bh[ni][0], bh[ni][1], gbhB + r0 * 4u);
            lds64(bl[ni][0], bl[ni][1], gblB + r0 * 4u);
        }
#pragma unroll
        for (int mi = 0; mi < 2; ++mi) {
            uint32_t ah[4], al[4];
            uint32_t r0 = (warpM2 + mi * 16u + lg) * 36u + kw;
            uint32_t r1 = r0 + 8u * 36u;
            lds64(ah[0], ah[2], a2hB + r0 * 4u);
            lds64(ah[1], ah[3], a2hB + r1 * 4u);
            lds64(al[0], al[2], a2lB + r0 * 4u);
            lds64(al[1], al[3], a2lB + r1 * 4u);
#pragma unroll
            for (int ni = 0; ni < 2; ++ni) {
                mma_f16(t4[mi][ni], ah, bh[ni]);
                mma_f16(t4[mi][ni], ah, bl[ni]);
                mma_f16(t4[mi][ni], al, bh[ni]);
            }
        }
    }

    {
        float pr[2][2];
#pragma unroll
        for (int mi = 0; mi < 2; ++mi) { pr[mi][0] = 0.f; pr[mi][1] = 0.f; }
#pragma unroll
        for (int mi = 0; mi < 2; ++mi)
#pragma unroll
            for (int ni = 0; ni < 2; ++ni) {
                int cc = warpN2 + ni * 8 + lt * 2;
                int r0 = warpM2 + mi * 16 + lg;
                int r1 = r0 + 8;
                pr[mi][0] = fmaf(t4[mi][ni][0], shf[P_AH + r0 * 68 + cc],
                             fmaf(t4[mi][ni][1], shf[P_AH + r0 * 68 + cc + 1], pr[mi][0]));
                pr[mi][1] = fmaf(t4[mi][ni][2], shf[P_AH + r1 * 68 + cc],
                             fmaf(t4[mi][ni][3], shf[P_AH + r1 * 68 + cc + 1], pr[mi][1]));
            }
#pragma unroll
        for (int mi = 0; mi < 2; ++mi)
#pragma unroll
            for (int rr = 0; rr < 2; ++rr) {
                pr[mi][rr] += __shfl_xor_sync(FULL, pr[mi][rr], 1);
                pr[mi][rr] += __shfl_xor_sync(FULL, pr[mi][rr], 2);
            }
        if (lt == 0) {
            int cg = wid >> 1;
#pragma unroll
            for (int mi = 0; mi < 2; ++mi) {
                int r0 = warpM2 + mi * 16 + lg;
                shf[P_PB + cg * 64 + r0] = pr[mi][0];
                shf[P_PB + cg * 64 + r0 + 8] = pr[mi][1];
            }
        }
    }
    __syncthreads();

    if (tid < 64) {
        float w2sq = shf[P_PB + tid] + shf[P_PB + 64 + tid] +
                     shf[P_PB + 128 + tid] + shf[P_PB + 192 + tid];
        float w2 = sqrtf(fmaxf(w2sq, 0.f));
        float den = fmaxf(g_w1[i * NL + tid] * w2, 1e-8f);
        float cs = shf[P_CM + tid] / den;
        shf[P_ES + tid] = __expf(5.f * cs);
    }
    __syncthreads();
    if (tid == 0) {
        float z = 0.f;
#pragma unroll
        for (int q = 0; q < 64; q++) z += shf[P_ES + q];
        g_sim[j * NB + i] = 10.f * logf(z);
    }

    if (i == j) {
        float* ap = out + 1 + (size_t)i * NL * NL;
#pragma unroll
        for (int m = 0; m < 4; m++)
#pragma unroll
            for (int n = 0; n < 4; n++)
                ap[(row0 + m) * NL + col0 + n] = shf[P_AH + (row0 + m) * 68 + col0 + n];
    }
}

// ===========================================================================
// loss (R10)
// ===========================================================================
__global__ __launch_bounds__(256) void loss_kernel(float* __restrict__ out) {
    __shared__ float sm[64 * 64];
    __shared__ float sh[64];
    const int tid = threadIdx.x;
#pragma unroll
    for (int r = 0; r < 4; ++r) {
        int idx = tid * 4 + r * 1024;
        *reinterpret_cast<float4*>(sm + idx) = *reinterpret_cast<const float4*>(g_sim + idx);
    }
    __syncthreads();
    if (tid < 64) {
        int t = tid;
        float m1 = -1e30f, m2 = -1e30f;
#pragma unroll 8
        for (int b = 0; b < NB; b++) {
            m1 = fmaxf(m1, sm[t * NB + b]);
            m2 = fmaxf(m2, sm[b * NB + t]);
        }
        float z1 = 0.f, z2 = 0.f;
#pragma unroll 8
        for (int b = 0; b < NB; b++) {
            z1 += fexp(sm[t * NB + b] - m1);
            z2 += fexp(sm[b * NB + t] - m2);
        }
        float dg = sm[t * NB + t];
        sh[t] = (dg - (m1 + logf(z1))) + (dg - (m2 + logf(z2)));
    }
    __syncthreads();
    if (tid == 0) {
        float s = 0.f;
#pragma unroll
        for (int q = 0; q < NB; q++) s += sh[q];
        out[0] = -s / (2.f * (float)NB);
    }
}

extern "C" void kernel_launch(void* const* d_in, const int* in_sizes, int n_in,
                              void* d_out, int out_size) {
    const float* ecg = (const float*)d_in[0];
    const float* sent = (const float*)d_in[1];
    float* out = (float*)d_out;

    cudaFuncSetAttribute(s_gemm_kernel, cudaFuncAttributeMaxDynamicSharedMemorySize, SMEM_TOTAL);
    cudaFuncSetAttribute(pair_kernel, cudaFuncAttributeMaxDynamicSharedMemorySize, PAIR_SMEM);

    s_gemm_kernel<<<dim3(32, 32), 256, SMEM_TOTAL>>>(ecg, sent);
    gram_kernel<<<256, 256>>>(ecg, sent);
    pair_kernel<<<dim3(64, 64), 256, PAIR_SMEM>>>(out);
    loss_kernel<<<1, 256>>>(out);
}

// round 16
// speedup vs baseline: 1.0049x; 1.0049x over previous
#include <cuda_runtime.h>
#include <cuda_fp16.h>
#include <math.h>
#include <cstdint>

#define NB 64
#define NL 64
#define ND 512

// ---------------- device scratch ----------------
__device__ float g_G[NB * NL * NL];
__device__ float g_w1[NB * NL];
__device__ float g_sim[NB * NB];
__device__ float g_S[4096u * 4096u];

// ---------------- helpers ----------------
__device__ __forceinline__ uint32_t smem_u32(const void* p) {
    uint32_t a;
    asm("{ .reg .u64 t; cvta.to.shared.u64 t, %1; cvt.u32.u64 %0, t; }" : "=r"(a) : "l"(p));
    return a;
}
__device__ __forceinline__ void lds64nv(uint32_t& x, uint32_t& y, uint32_t a) {
    asm("ld.shared.v2.b32 {%0, %1}, [%2];" : "=r"(x), "=r"(y) : "r"(a));
}
__device__ __forceinline__ void lds64(uint32_t& x, uint32_t& y, uint32_t a) {
    asm volatile("ld.shared.v2.b32 {%0, %1}, [%2];" : "=r"(x), "=r"(y) : "r"(a));
}
__device__ __forceinline__ void sts128v(uint32_t a, uint32_t x, uint32_t y, uint32_t z, uint32_t w) {
    asm volatile("st.shared.v4.b32 [%0], {%1, %2, %3, %4};"
                 :: "r"(a), "r"(x), "r"(y), "r"(z), "r"(w) : "memory");
}
__device__ __forceinline__ uint32_t pkh(__half a, __half b) {
    __half2 h = __halves2half2(a, b);
    return *reinterpret_cast<uint32_t*>(&h);
}
__device__ __forceinline__ void mma_f16(float* c, const uint32_t* a, const uint32_t* b) {
    asm volatile(
        "mma.sync.aligned.m16n8k16.row.col.f32.f16.f16.f32 "
        "{%0,%1,%2,%3}, {%4,%5,%6,%7}, {%8,%9}, {%0,%1,%2,%3};"
        : "+f"(c[0]), "+f"(c[1]), "+f"(c[2]), "+f"(c[3])
        : "r"(a[0]), "r"(a[1]), "r"(a[2]), "r"(a[3]), "r"(b[0]), "r"(b[1]));
}

// FMA-pipe exp for x <= 0 (clamped at -87), rel err ~1e-7.
__device__ __forceinline__ float fexp(float x) {
    x = fmaxf(x, -87.0f);
    float t = fmaf(x, 1.4426950408889634f, 12582912.0f);
    float n = t - 12582912.0f;
    float f = fmaf(x, 1.4426950408889634f, -n);
    float p = 1.33978935e-3f;
    p = fmaf(p, f, 9.67518295e-3f);
    p = fmaf(p, f, 5.55041086e-2f);
    p = fmaf(p, f, 2.40226507e-1f);
    p = fmaf(p, f, 6.93147182e-1f);
    p = fmaf(p, f, 1.0f);
    int ni = __float_as_int(t) - 0x4B400000;
    float s = __int_as_float((ni + 127) << 23);
    return p * s;
}

// ===========================================================================
// Kernel A: S-GEMM — exact R14 (294 us) version.
// ===========================================================================
#define BK 32
#define NCH (ND / BK)
#define ROWW 24u
#define OFF_AHI 0u
#define OFF_ALO 12288u
#define OFF_BHI 24576u
#define OFF_BLO 36864u
#define STAGE_B 49152u
#define SMEM_TOTAL (2u * STAGE_B)

__global__ __launch_bounds__(256, 1) void s_gemm_kernel(const float* __restrict__ ecg,
                                                        const float* __restrict__ sent) {
    extern __shared__ char dsm[];
    const uint32_t sbase = smem_u32(dsm);

    const int tid = threadIdx.x;
    const int wid = tid >> 5, lane = tid & 31;
    const int tileN = blockIdx.x;
    const int tileM = blockIdx.y;

    const int grow = tid >> 1;
    const int g = tid & 1;
    const float* Ag = sent + ((size_t)tileM * 128 + grow) * ND + g * 16;
    const float* Bg = ecg + ((size_t)tileN * 128 + grow) * ND + g * 16;
    const uint32_t wbB = ((uint32_t)grow * ROWW + (uint32_t)g * 12u) * 4u;

    const uint32_t warpM = (uint32_t)(wid & 1) * 64u;
    const uint32_t warpN = (uint32_t)(wid >> 1) * 32u;
    const uint32_t lg = lane >> 2, lt = lane & 3;

    float acc[4][4][4];
#pragma unroll
    for (int mi = 0; mi < 4; ++mi)
#pragma unroll
        for (int ni = 0; ni < 4; ++ni)
#pragma unroll
            for (int r = 0; r < 4; ++r) acc[mi][ni][r] = 0.f;

    float4 ra[4], rb[4];
    auto ldg_chunk = [&](int t) {
#pragma unroll
        for (int r = 0; r < 4; ++r) {
            ra[r] = *reinterpret_cast<const float4*>(Ag + t * BK + r * 4);
            rb[r] = *reinterpret_cast<const float4*>(Bg + t * BK + r * 4);
        }
    };

    auto cvt_store = [&](const float4* q, uint32_t hiB, uint32_t loB) {
        float v[16];
#pragma unroll
        for (int r = 0; r < 4; ++r) {
            v[r * 4 + 0] = q[r].x; v[r * 4 + 1] = q[r].y;
            v[r * 4 + 2] = q[r].z; v[r * 4 + 3] = q[r].w;
        }
        __half H[16], L[16];
#pragma unroll
        for (int idx = 0; idx < 16; ++idx) {
            __half h = __float2half_rn(v[idx]);
            H[idx] = h;
            L[idx] = __float2half_rn(v[idx] - __half2float(h));
        }
        uint32_t W0 = pkh(H[0], H[1]), W1 = pkh(H[8], H[9]);
        uint32_t W2 = pkh(H[2], H[3]), W3 = pkh(H[10], H[11]);
        uint32_t W4 = pkh(H[4], H[5]), W5 = pkh(H[12], H[13]);
        uint32_t W6 = pkh(H[6], H[7]), W7 = pkh(H[14], H[15]);
        sts128v(hiB + wbB, W0, W1, W2, W3);
        sts128v(hiB + wbB + 16u, W4, W5, W6, W7);
        uint32_t X0 = pkh(L[0], L[1]), X1 = pkh(L[8], L[9]);
        uint32_t X2 = pkh(L[2], L[3]), X3 = pkh(L[10], L[11]);
        uint32_t X4 = pkh(L[4], L[5]), X5 = pkh(L[12], L[13]);
        uint32_t X6 = pkh(L[6], L[7]), X7 = pkh(L[14], L[15]);
        sts128v(loB + wbB, X0, X1, X2, X3);
        sts128v(loB + wbB + 16u, X4, X5, X6, X7);
    };

    auto sts_chunk = [&](uint32_t st) {
        cvt_store(ra, st + OFF_AHI, st + OFF_ALO);
        cvt_store(rb, st + OFF_BHI, st + OFF_BLO);
    };

    ldg_chunk(0);
    sts_chunk(sbase);
    ldg_chunk(1);
    __syncthreads();

    for (int t = 0; t < NCH; ++t) {
        const uint32_t st = sbase + (uint32_t)(t & 1) * STAGE_B;

#pragma unroll
        for (int s = 0; s < 2; ++s) {
            uint32_t ah[4][4], al[4][4], bh[4][2], bl[4][2];
            const uint32_t kw = (uint32_t)s * 12u + 2u * lt;
#pragma unroll
            for (int mi = 0; mi < 4; ++mi) {
                uint32_t r0 = (warpM + mi * 16u + lg) * ROWW + kw;
                uint32_t r1 = r0 + 8u * ROWW;
                lds64nv(ah[mi][0], ah[mi][2], st + OFF_AHI + r0 * 4u);
                lds64nv(ah[mi][1], ah[mi][3], st + OFF_AHI + r1 * 4u);
                lds64nv(al[mi][0], al[mi][2], st + OFF_ALO + r0 * 4u);
                lds64nv(al[mi][1], al[mi][3], st + OFF_ALO + r1 * 4u);
            }
#pragma unroll
            for (int ni = 0; ni < 4; ++ni) {
                uint32_t r0 = (warpN + ni * 8u + lg) * ROWW + kw;
                lds64nv(bh[ni][0], bh[ni][1], st + OFF_BHI + r0 * 4u);
                lds64nv(bl[ni][0], bl[ni][1], st + OFF_BLO + r0 * 4u);
            }
#pragma unroll
            for (int mi = 0; mi < 4; ++mi)
#pragma unroll
                for (int ni = 0; ni < 4; ++ni) {
                    mma_f16(acc[mi][ni], ah[mi], bh[ni]);
                    mma_f16(acc[mi][ni], ah[mi], bl[ni]);
                    mma_f16(acc[mi][ni], al[mi], bh[ni]);
                }
        }

        if (t + 1 < NCH) sts_chunk(sbase + (uint32_t)((t + 1) & 1) * STAGE_B);
        if (t + 2 < NCH) ldg_chunk(t + 2);
        __syncthreads();
    }

    const size_t rbase = (size_t)tileM * 128 + warpM + lg;
    const size_t cbase = (size_t)tileN * 128 + warpN + lt * 2;
#pragma unroll
    for (int mi = 0; mi < 4; ++mi)
#pragma unroll
        for (int ni = 0; ni < 4; ++ni) {
            float* p0 = g_S + (rbase + mi * 16) * 4096u + cbase + ni * 8;
            *reinterpret_cast<float2*>(p0) = make_float2(acc[mi][ni][0], acc[mi][ni][1]);
            *reinterpret_cast<float2*>(p0 + 8 * 4096u) = make_float2(acc[mi][ni][2], acc[mi][ni][3]);
        }
}

// ===========================================================================
// Kernel B: Gram quadrants (256 CTAs) + w1 norms.
// ===========================================================================
__global__ __launch_bounds__(256) void gram_kernel(const float* __restrict__ ecg,
                                                   const float* __restrict__ sent) {
    __shared__ float sA[32 * 66];
    __shared__ float sB[32 * 66];
    const int j = blockIdx.x >> 2;
    const int quad = blockIdx.x & 3;
    const int qr = (quad >> 1) * 32, qc = (quad & 1) * 32;
    const int tid = threadIdx.x;
    const int tx = tid & 15, ty = tid >> 4;
    const int r0 = ty * 2, c0 = tx * 2;
    const float* base = ecg + (size_t)j * NL * ND;

    float c00 = 0.f, c01 = 0.f, c10 = 0.f, c11 = 0.f;
    const int lrow = tid >> 3;
    const int lcol = (tid & 7) * 8;

    for (int kt = 0; kt < ND; kt += 64) {
        __syncthreads();
#pragma unroll
        for (int r = 0; r < 2; ++r) {
            float4 va = *reinterpret_cast<const float4*>(base + (qr + lrow) * ND + kt + lcol + r * 4);
            sA[lrow * 66 + lcol + r * 4 + 0] = va.x;
            sA[lrow * 66 + lcol + r * 4 + 1] = va.y;
            sA[lrow * 66 + lcol + r * 4 + 2] = va.z;
            sA[lrow * 66 + lcol + r * 4 + 3] = va.w;
            float4 vb = *reinterpret_cast<const float4*>(base + (qc + lrow) * ND + kt + lcol + r * 4);
            sB[lrow * 66 + lcol + r * 4 + 0] = vb.x;
            sB[lrow * 66 + lcol + r * 4 + 1] = vb.y;
            sB[lrow * 66 + lcol + r * 4 + 2] = vb.z;
            sB[lrow * 66 + lcol + r * 4 + 3] = vb.w;
        }
        __syncthreads();
#pragma unroll 8
        for (int k = 0; k < 64; ++k) {
            float a0 = sA[r0 * 66 + k], a1 = sA[(r0 + 1) * 66 + k];
            float b0 = sB[c0 * 66 + k], b1 = sB[(c0 + 1) * 66 + k];
            c00 = fmaf(a0, b0, c00);
            c01 = fmaf(a0, b1, c01);
            c10 = fmaf(a1, b0, c10);
            c11 = fmaf(a1, b1, c11);
        }
    }
    float* Gp = g_G + (size_t)j * NL * NL;
    Gp[(qr + r0) * NL + qc + c0] = c00;
    Gp[(qr + r0) * NL + qc + c0 + 1] = c01;
    Gp[(qr + r0 + 1) * NL + qc + c0] = c10;
    Gp[(qr + r0 + 1) * NL + qc + c0 + 1] = c11;

    if (quad == 0) {
        int q = tid >> 2;
        int p = tid & 3;
        const float* sp = sent + (size_t)j * NL * ND + q * ND + p * 128;
        float s = 0.f;
#pragma unroll 8
        for (int t2 = 0; t2 < 32; t2++) {
            float4 v = *reinterpret_cast<const float4*>(sp + t2 * 4);
            s = fmaf(v.x, v.x, fmaf(v.y, v.y, fmaf(v.z, v.z, fmaf(v.w, v.w, s))));
        }
        s += __shfl_xor_sync(0xffffffffu, s, 1);
        s += __shfl_xor_sync(0xffffffffu, s, 2);
        if (p == 0) g_w1[j * NL + q] = sqrtf(s);
    }
}

// ===========================================================================
// Kernel C: pair epilogue — smem trimmed to 56.6 KB, regs capped for occ 4.
// ===========================================================================
#define P_AH 0
#define P_A2H 4224
#define P_A2L 6528
#define P_GBH 8832
#define P_GBL 11136
#define P_PB 13440
#define P_CM 13968
#define P_CZ 14032
#define P_ES 14096
#define PAIR_SMEM (14160 * 4)

__global__ __launch_bounds__(256, 4) void pair_kernel(float* __restrict__ out) {
    extern __shared__ float shf[];
    uint32_t* shw = reinterpret_cast<uint32_t*>(shf);
    const unsigned FULL = 0xffffffffu;

    const int i = blockIdx.x, j = blockIdx.y;
    const int tid = threadIdx.x;
    const int wid = tid >> 5, lane = tid & 31;
    const int tx = tid & 15, ty = tid >> 4;
    const int row0 = ty * 4, col0 = tx * 4;

    const int gg8 = (col0 >> 4) * 8;
    const int pp = col0 & 15;
    const int wsel = (pp < 8) ? pp : pp - 7;

    float c[4][4];
    const float* Sp = g_S + ((size_t)i * 64) * 4096u + (size_t)j * 64;
#pragma unroll
    for (int m = 0; m < 4; m++) {
        float4 v4 = *reinterpret_cast<const float4*>(Sp + (size_t)(row0 + m) * 4096u + col0);
        c[m][0] = v4.x; c[m][1] = v4.y; c[m][2] = v4.z; c[m][3] = v4.w;
    }

    {
        const float* Gp = g_G + (size_t)j * NL * NL;
        const int f = tx * 4;
        const int fg8 = (f >> 4) * 8;
        const int fp = f & 15;
        const int fw = (fp < 8) ? fp : fp - 7;
#pragma unroll
        for (int r = 0; r < 4; ++r) {
            int q = ty + r * 16;
            float4 gq = *reinterpret_cast<const float4*>(Gp + q * NL + f);
            __half h0 = __float2half_rn(gq.x), h1 = __float2half_rn(gq.y);
            __half h2 = __float2half_rn(gq.z), h3 = __float2half_rn(gq.w);
            __half l0 = __float2half_rn(gq.x - __half2float(h0));
            __half l1 = __float2half_rn(gq.y - __half2float(h1));
            __half l2 = __float2half_rn(gq.z - __half2float(h2));
            __half l3 = __float2half_rn(gq.w - __half2float(h3));
            int wb = q * 36 + fg8 + fw;
            shw[P_GBH + wb] = pkh(h0, h1);
            shw[P_GBH + wb + 2] = pkh(h2, h3);
            shw[P_GBL + wb] = pkh(l0, l1);
            shw[P_GBL + wb + 2] = pkh(l2, l3);
        }
    }

    // ---- col max ----
    {
        float pm[4];
#pragma unroll
        for (int n = 0; n < 4; n++) {
            pm[n] = c[0][n];
#pragma unroll
            for (int m = 1; m < 4; m++) pm[n] = fmaxf(pm[n], c[m][n]);
            pm[n] = fmaxf(pm[n], __shfl_xor_sync(FULL, pm[n], 16));
        }
        if (lane < 16) {
#pragma unroll
            for (int n = 0; n < 4; n++) shf[P_PB + wid * 66 + col0 + n] = pm[n];
        }
    }
    __syncthreads();
    if (tid < 64) {
        float m = -1e30f;
#pragma unroll
        for (int p = 0; p < 8; p++) m = fmaxf(m, shf[P_PB + p * 66 + tid]);
        shf[P_CM + tid] = m;
    }
    __syncthreads();

    // ---- e1 once; col sums ----
    float v[4][4];
    {
        float ps[4];
#pragma unroll
        for (int n = 0; n < 4; n++) {
            float cm = shf[P_CM + col0 + n];
            float s = 0.f;
#pragma unroll
            for (int m = 0; m < 4; m++) {
                float e = fexp(c[m][n] - cm);
                v[m][n] = e;
                s += e;
            }
            ps[n] = s + __shfl_xor_sync(FULL, s, 16);
        }
        if (lane < 16) {
#pragma unroll
            for (int n = 0; n < 4; n++) shf[P_PB + wid * 66 + col0 + n] = ps[n];
        }
    }
    __syncthreads();
    if (tid < 64) {
        float z = 0.f;
#pragma unroll
        for (int p = 0; p < 8; p++) z += shf[P_PB + p * 66 + tid];
        shf[P_CZ + tid] = 4.f / z;
    }
    __syncthreads();

#pragma unroll
    for (int n = 0; n < 4; n++) {
        float zr = shf[P_CZ + col0 + n];
#pragma unroll
        for (int m = 0; m < 4; m++) v[m][n] *= zr;
    }

    float rm[4];
#pragma unroll
    for (int m = 0; m < 4; m++) {
        float pm = v[m][0];
#pragma unroll
        for (int n = 1; n < 4; n++) pm = fmaxf(pm, v[m][n]);
#pragma unroll
        for (int off = 1; off < 16; off <<= 1)
            pm = fmaxf(pm, __shfl_xor_sync(FULL, pm, off));
        rm[m] = pm;
    }

    float rz[4];
#pragma unroll
    for (int m = 0; m < 4; m++) {
        float s = 0.f;
#pragma unroll
        for (int n = 0; n < 4; n++) {
            float e = fexp(v[m][n] - rm[m]);
            v[m][n] = e;
            s += e;
        }
#pragma unroll
        for (int off = 1; off < 16; off <<= 1)
            s += __shfl_xor_sync(FULL, s, off);
        rz[m] = 1.f / s;
    }

#pragma unroll
    for (int m = 0; m < 4; m++) {
        float w12p = 0.f;
        float a2v[4];
#pragma unroll
        for (int n = 0; n < 4; n++) {
            float a2 = v[m][n] * rz[m];
            a2v[n] = a2;
            v[m][n] = a2;
            w12p = fmaf(a2, c[m][n], w12p);
            shf[P_AH + (row0 + m) * 66 + col0 + n] = a2;
        }
#pragma unroll
        for (int off = 1; off < 16; off <<= 1)
            w12p += __shfl_xor_sync(FULL, w12p, off);
        if (tx == 0) shf[P_CM + row0 + m] = w12p;
        __half h0 = __float2half_rn(a2v[0]), h1 = __float2half_rn(a2v[1]);
        __half h2 = __float2half_rn(a2v[2]), h3 = __float2half_rn(a2v[3]);
        __half l0 = __float2half_rn(a2v[0] - __half2float(h0));
        __half l1 = __float2half_rn(a2v[1] - __half2float(h1));
        __half l2 = __float2half_rn(a2v[2] - __half2float(h2));
        __half l3 = __float2half_rn(a2v[3] - __half2float(h3));
        int wb = (row0 + m) * 36 + gg8 + wsel;
        shw[P_A2H + wb] = pkh(h0, h1);
        shw[P_A2H + wb + 2] = pkh(h2, h3);
        shw[P_A2L + wb] = pkh(l0, l1);
        shw[P_A2L + wb + 2] = pkh(l2, l3);
    }
    __syncthreads();

    // ---- GEMM2 on tensor ----
    const uint32_t warpM2 = (uint32_t)(wid & 1) * 32u;
    const uint32_t warpN2 = (uint32_t)(wid >> 1) * 16u;
    const uint32_t lg = lane >> 2, lt = lane & 3;
    const uint32_t a2hB = smem_u32(shw + P_A2H);
    const uint32_t a2lB = smem_u32(shw + P_A2L);
    const uint32_t gbhB = smem_u32(shw + P_GBH);
    const uint32_t gblB = smem_u32(shw + P_GBL);

    float t4[2][2][4];
#pragma unroll
    for (int mi = 0; mi < 2; ++mi)
#pragma unroll
        for (int ni = 0; ni < 2; ++ni)
#pragma unroll
            for (int r = 0; r < 4; ++r) t4[mi][ni][r] = 0.f;

#pragma unroll
    for (int kk = 0; kk < 4; ++kk) {
        const uint32_t kw = (uint32_t)kk * 8u + 2u * lt;
        uint32_t bh[2][2], bl[2][2];
#pragma unroll
        for (int ni = 0; ni < 2; ++ni) {
            uint32_t r0 = (warpN2 + ni * 8u + lg) * 36u + kw;
            lds64(bh[ni][0], bh[ni][1], gbhB + r0 * 4u);
            lds64(bl[ni][0], bl[ni][1], gblB + r0 * 4u);
        }
#pragma unroll
        for (int mi = 0; mi < 2; ++mi) {
            uint32_t ah[4], al[4];
            uint32_t r0 = (warpM2 + mi * 16u + lg) * 36u + kw;
            uint32_t r1 = r0 + 8u * 36u;
            lds64(ah[0], ah[2], a2hB + r0 * 4u);
            lds64(ah[1], ah[3], a2hB + r1 * 4u);
            lds64(al[0], al[2], a2lB + r0 * 4u);
            lds64(al[1], al[3], a2lB + r1 * 4u);
#pragma unroll
            for (int ni = 0; ni < 2; ++ni) {
                mma_f16(t4[mi][ni], ah, bh[ni]);
                mma_f16(t4[mi][ni], ah, bl[ni]);
                mma_f16(t4[mi][ni], al, bh[ni]);
            }
        }
    }

    {
        float pr[2][2];
#pragma unroll
        for (int mi = 0; mi < 2; ++mi) { pr[mi][0] = 0.f; pr[mi][1] = 0.f; }
#pragma unroll
        for (int mi = 0; mi < 2; ++mi)
#pragma unroll
            for (int ni = 0; ni < 2; ++ni) {
                int cc = warpN2 + ni * 8 + lt * 2;
                int r0 = warpM2 + mi * 16 + lg;
                int r1 = r0 + 8;
                pr[mi][0] = fmaf(t4[mi][ni][0], shf[P_AH + r0 * 66 + cc],
                             fmaf(t4[mi][ni][1], shf[P_AH + r0 * 66 + cc + 1], pr[mi][0]));
                pr[mi][1] = fmaf(t4[mi][ni][2], shf[P_AH + r1 * 66 + cc],
                             fmaf(t4[mi][ni][3], shf[P_AH + r1 * 66 + cc + 1], pr[mi][1]));
            }
#pragma unroll
        for (int mi = 0; mi < 2; ++mi)
#pragma unroll
            for (int rr = 0; rr < 2; ++rr) {
                pr[mi][rr] += __shfl_xor_sync(FULL, pr[mi][rr], 1);
                pr[mi][rr] += __shfl_xor_sync(FULL, pr[mi][rr], 2);
            }
        if (lt == 0) {
            int cg = wid >> 1;
#pragma unroll
            for (int mi = 0; mi < 2; ++mi) {
                int r0 = warpM2 + mi * 16 + lg;
                shf[P_PB + cg * 64 + r0] = pr[mi][0];
                shf[P_PB + cg * 64 + r0 + 8] = pr[mi][1];
            }
        }
    }
    __syncthreads();

    if (tid < 64) {
        float w2sq = shf[P_PB + tid] + shf[P_PB + 64 + tid] +
                     shf[P_PB + 128 + tid] + shf[P_PB + 192 + tid];
        float w2 = sqrtf(fmaxf(w2sq, 0.f));
        float den = fmaxf(g_w1[i * NL + tid] * w2, 1e-8f);
        float cs = shf[P_CM + tid] / den;
        shf[P_ES + tid] = __expf(5.f * cs);
    }
    __syncthreads();
    if (tid == 0) {
        float z = 0.f;
#pragma unroll
        for (int q = 0; q < 64; q++) z += shf[P_ES + q];
        g_sim[j * NB + i] = 10.f * logf(z);
    }

    if (i == j) {
        float* ap = out + 1 + (size_t)i * NL * NL;
#pragma unroll
        for (int m = 0; m < 4; m++)
#pragma unroll
            for (int n = 0; n < 4; n++)
                ap[(row0 + m) * NL + col0 + n] = shf[P_AH + (row0 + m) * 66 + col0 + n];
    }
}

// ===========================================================================
// loss
// ===========================================================================
__global__ __launch_bounds__(256) void loss_kernel(float* __restrict__ out) {
    __shared__ float sm[64 * 64];
    __shared__ float sh[64];
    const int tid = threadIdx.x;
#pragma unroll
    for (int r = 0; r < 4; ++r) {
        int idx = tid * 4 + r * 1024;
        *reinterpret_cast<float4*>(sm + idx) = *reinterpret_cast<const float4*>(g_sim + idx);
    }
    __syncthreads();
    if (tid < 64) {
        int t = tid;
        float m1 = -1e30f, m2 = -1e30f;
#pragma unroll 8
        for (int b = 0; b < NB; b++) {
            m1 = fmaxf(m1, sm[t * NB + b]);
            m2 = fmaxf(m2, sm[b * NB + t]);
        }
        float z1 = 0.f, z2 = 0.f;
#pragma unroll 8
        for (int b = 0; b < NB; b++) {
            z1 += fexp(sm[t * NB + b] - m1);
            z2 += fexp(sm[b * NB + t] - m2);
        }
        float dg = sm[t * NB + t];
        sh[t] = (dg - (m1 + logf(z1))) + (dg - (m2 + logf(z2)));
    }
    __syncthreads();
    if (tid == 0) {
        float s = 0.f;
#pragma unroll
        for (int q = 0; q < NB; q++) s += sh[q];
        out[0] = -s / (2.f * (float)NB);
    }
}

extern "C" void kernel_launch(void* const* d_in, const int* in_sizes, int n_in,
                              void* d_out, int out_size) {
    const float* ecg = (const float*)d_in[0];
    const float* sent = (const float*)d_in[1];
    float* out = (float*)d_out;

    cudaFuncSetAttribute(s_gemm_kernel, cudaFuncAttributeMaxDynamicSharedMemorySize, SMEM_TOTAL);
    cudaFuncSetAttribute(pair_kernel, cudaFuncAttributeMaxDynamicSharedMemorySize, PAIR_SMEM);

    s_gemm_kernel<<<dim3(32, 32), 256, SMEM_TOTAL>>>(ecg, sent);
    gram_kernel<<<256, 256>>>(ecg, sent);
    pair_kernel<<<dim3(64, 64), 256, PAIR_SMEM>>>(out);
    loss_kernel<<<1, 256>>>(out);
}

// round 17
// speedup vs baseline: 1.0311x; 1.0261x over previous
#include <cuda_runtime.h>
#include <cuda_fp16.h>
#include <math.h>
#include <cstdint>

#define NB 64
#define NL 64
#define ND 512

// ---------------- device scratch ----------------
__device__ float g_G[NB * NL * NL];
__device__ float g_w1[NB * NL];
__device__ float g_sim[NB * NB];
__device__ float g_S[4096u * 4096u];

// ---------------- helpers ----------------
__device__ __forceinline__ uint32_t smem_u32(const void* p) {
    uint32_t a;
    asm("{ .reg .u64 t; cvta.to.shared.u64 t, %1; cvt.u32.u64 %0, t; }" : "=r"(a) : "l"(p));
    return a;
}
__device__ __forceinline__ void lds64nv(uint32_t& x, uint32_t& y, uint32_t a) {
    asm("ld.shared.v2.b32 {%0, %1}, [%2];" : "=r"(x), "=r"(y) : "r"(a));
}
__device__ __forceinline__ void lds64(uint32_t& x, uint32_t& y, uint32_t a) {
    asm volatile("ld.shared.v2.b32 {%0, %1}, [%2];" : "=r"(x), "=r"(y) : "r"(a));
}
__device__ __forceinline__ void sts128v(uint32_t a, uint32_t x, uint32_t y, uint32_t z, uint32_t w) {
    asm volatile("st.shared.v4.b32 [%0], {%1, %2, %3, %4};"
                 :: "r"(a), "r"(x), "r"(y), "r"(z), "r"(w) : "memory");
}
__device__ __forceinline__ uint32_t pkh(__half a, __half b) {
    __half2 h = __halves2half2(a, b);
    return *reinterpret_cast<uint32_t*>(&h);
}
__device__ __forceinline__ void mma_f16(float* c, const uint32_t* a, const uint32_t* b) {
    asm volatile(
        "mma.sync.aligned.m16n8k16.row.col.f32.f16.f16.f32 "
        "{%0,%1,%2,%3}, {%4,%5,%6,%7}, {%8,%9}, {%0,%1,%2,%3};"
        : "+f"(c[0]), "+f"(c[1]), "+f"(c[2]), "+f"(c[3])
        : "r"(a[0]), "r"(a[1]), "r"(a[2]), "r"(a[3]), "r"(b[0]), "r"(b[1]));
}

// FMA-pipe exp for x <= 0 (clamped at -87), rel err ~1e-7.
__device__ __forceinline__ float fexp(float x) {
    x = fmaxf(x, -87.0f);
    float t = fmaf(x, 1.4426950408889634f, 12582912.0f);
    float n = t - 12582912.0f;
    float f = fmaf(x, 1.4426950408889634f, -n);
    float p = 1.33978935e-3f;
    p = fmaf(p, f, 9.67518295e-3f);
    p = fmaf(p, f, 5.55041086e-2f);
    p = fmaf(p, f, 2.40226507e-1f);
    p = fmaf(p, f, 6.93147182e-1f);
    p = fmaf(p, f, 1.0f);
    int ni = __float_as_int(t) - 0x4B400000;
    float s = __int_as_float((ni + 127) << 23);
    return p * s;
}

// ===========================================================================
// Kernel A: S-GEMM — 4-stage smem pipeline, one barrier per 2 chunks.
// ===========================================================================
#define BK 32
#define NCH (ND / BK)
#define ROWW 24u
#define OFF_AHI 0u
#define OFF_ALO 12288u
#define OFF_BHI 24576u
#define OFF_BLO 36864u
#define STAGE_B 49152u
#define SMEM_TOTAL (4u * STAGE_B)   // 196608

__global__ __launch_bounds__(256, 1) void s_gemm_kernel(const float* __restrict__ ecg,
                                                        const float* __restrict__ sent) {
    extern __shared__ char dsm[];
    const uint32_t sbase = smem_u32(dsm);

    const int tid = threadIdx.x;
    const int wid = tid >> 5, lane = tid & 31;
    const int tileN = blockIdx.x;
    const int tileM = blockIdx.y;

    const int grow = tid >> 1;
    const int g = tid & 1;
    const float* Ag = sent + ((size_t)tileM * 128 + grow) * ND + g * 16;
    const float* Bg = ecg + ((size_t)tileN * 128 + grow) * ND + g * 16;
    const uint32_t wbB = ((uint32_t)grow * ROWW + (uint32_t)g * 12u) * 4u;

    const uint32_t warpM = (uint32_t)(wid & 1) * 64u;
    const uint32_t warpN = (uint32_t)(wid >> 1) * 32u;
    const uint32_t lg = lane >> 2, lt = lane & 3;

    float acc[4][4][4];
#pragma unroll
    for (int mi = 0; mi < 4; ++mi)
#pragma unroll
        for (int ni = 0; ni < 4; ++ni)
#pragma unroll
            for (int r = 0; r < 4; ++r) acc[mi][ni][r] = 0.f;

    float4 rA[2][4], rB[2][4];   // two staging register sets
    auto ldg_chunk = [&](int t, int s) {
#pragma unroll
        for (int r = 0; r < 4; ++r) {
            rA[s][r] = *reinterpret_cast<const float4*>(Ag + t * BK + r * 4);
            rB[s][r] = *reinterpret_cast<const float4*>(Bg + t * BK + r * 4);
        }
    };

    auto cvt_store = [&](const float4* q, uint32_t hiB, uint32_t loB) {
        float v[16];
#pragma unroll
        for (int r = 0; r < 4; ++r) {
            v[r * 4 + 0] = q[r].x; v[r * 4 + 1] = q[r].y;
            v[r * 4 + 2] = q[r].z; v[r * 4 + 3] = q[r].w;
        }
        __half H[16], L[16];
#pragma unroll
        for (int idx = 0; idx < 16; ++idx) {
            __half h = __float2half_rn(v[idx]);
            H[idx] = h;
            L[idx] = __float2half_rn(v[idx] - __half2float(h));
        }
        uint32_t W0 = pkh(H[0], H[1]), W1 = pkh(H[8], H[9]);
        uint32_t W2 = pkh(H[2], H[3]), W3 = pkh(H[10], H[11]);
        uint32_t W4 = pkh(H[4], H[5]), W5 = pkh(H[12], H[13]);
        uint32_t W6 = pkh(H[6], H[7]), W7 = pkh(H[14], H[15]);
        sts128v(hiB + wbB, W0, W1, W2, W3);
        sts128v(hiB + wbB + 16u, W4, W5, W6, W7);
        uint32_t X0 = pkh(L[0], L[1]), X1 = pkh(L[8], L[9]);
        uint32_t X2 = pkh(L[2], L[3]), X3 = pkh(L[10], L[11]);
        uint32_t X4 = pkh(L[4], L[5]), X5 = pkh(L[12], L[13]);
        uint32_t X6 = pkh(L[6], L[7]), X7 = pkh(L[14], L[15]);
        sts128v(loB + wbB, X0, X1, X2, X3);
        sts128v(loB + wbB + 16u, X4, X5, X6, X7);
    };

    auto sts_chunk = [&](uint32_t st, int s) {
        cvt_store(rA[s], st + OFF_AHI, st + OFF_ALO);
        cvt_store(rB[s], st + OFF_BHI, st + OFF_BLO);
    };

    auto buf = [&](int t) { return sbase + (uint32_t)(t & 3) * STAGE_B; };

    // one chunk of fragment loads + MMAs
    auto mma_chunk = [&](uint32_t st) {
#pragma unroll
        for (int s = 0; s < 2; ++s) {
            uint32_t ah[4][4], al[4][4], bh[4][2], bl[4][2];
            const uint32_t kw = (uint32_t)s * 12u + 2u * lt;
#pragma unroll
            for (int mi = 0; mi < 4; ++mi) {
                uint32_t r0 = (warpM + mi * 16u + lg) * ROWW + kw;
                uint32_t r1 = r0 + 8u * ROWW;
                lds64nv(ah[mi][0], ah[mi][2], st + OFF_AHI + r0 * 4u);
                lds64nv(ah[mi][1], ah[mi][3], st + OFF_AHI + r1 * 4u);
                lds64nv(al[mi][0], al[mi][2], st + OFF_ALO + r0 * 4u);
                lds64nv(al[mi][1], al[mi][3], st + OFF_ALO + r1 * 4u);
            }
#pragma unroll
            for (int ni = 0; ni < 4; ++ni) {
                uint32_t r0 = (warpN + ni * 8u + lg) * ROWW + kw;
                lds64nv(bh[ni][0], bh[ni][1], st + OFF_BHI + r0 * 4u);
                lds64nv(bl[ni][0], bl[ni][1], st + OFF_BLO + r0 * 4u);
            }
#pragma unroll
            for (int mi = 0; mi < 4; ++mi)
#pragma unroll
                for (int ni = 0; ni < 4; ++ni) {
                    mma_f16(acc[mi][ni], ah[mi], bh[ni]);
                    mma_f16(acc[mi][ni], ah[mi], bl[ni]);
                    mma_f16(acc[mi][ni], al[mi], bh[ni]);
                }
        }
    };

    // prologue: chunks 0,1 staged; chunks 2,3 in regs
    ldg_chunk(0, 0);
    ldg_chunk(1, 1);
    sts_chunk(buf(0), 0);
    sts_chunk(buf(1), 1);
    ldg_chunk(2, 0);
    ldg_chunk(3, 1);
    __syncthreads();

    for (int t = 0; t < NCH; t += 2) {
        mma_chunk(buf(t));
        mma_chunk(buf(t + 1));

        if (t + 2 < NCH) {
            sts_chunk(buf(t + 2), 0);
            if (t + 4 < NCH) ldg_chunk(t + 4, 0);
        }
        if (t + 3 < NCH) {
            sts_chunk(buf(t + 3), 1);
            if (t + 5 < NCH) ldg_chunk(t + 5, 1);
        }
        __syncthreads();
    }

    const size_t rbase = (size_t)tileM * 128 + warpM + lg;
    const size_t cbase = (size_t)tileN * 128 + warpN + lt * 2;
#pragma unroll
    for (int mi = 0; mi < 4; ++mi)
#pragma unroll
        for (int ni = 0; ni < 4; ++ni) {
            float* p0 = g_S + (rbase + mi * 16) * 4096u + cbase + ni * 8;
            *reinterpret_cast<float2*>(p0) = make_float2(acc[mi][ni][0], acc[mi][ni][1]);
            *reinterpret_cast<float2*>(p0 + 8 * 4096u) = make_float2(acc[mi][ni][2], acc[mi][ni][3]);
        }
}

// ===========================================================================
// Kernel B: Gram quadrants (256 CTAs) + w1 norms.
// ===========================================================================
__global__ __launch_bounds__(256) void gram_kernel(const float* __restrict__ ecg,
                                                   const float* __restrict__ sent) {
    __shared__ float sA[32 * 66];
    __shared__ float sB[32 * 66];
    const int j = blockIdx.x >> 2;
    const int quad = blockIdx.x & 3;
    const int qr = (quad >> 1) * 32, qc = (quad & 1) * 32;
    const int tid = threadIdx.x;
    const int tx = tid & 15, ty = tid >> 4;
    const int r0 = ty * 2, c0 = tx * 2;
    const float* base = ecg + (size_t)j * NL * ND;

    float c00 = 0.f, c01 = 0.f, c10 = 0.f, c11 = 0.f;
    const int lrow = tid >> 3;
    const int lcol = (tid & 7) * 8;

    for (int kt = 0; kt < ND; kt += 64) {
        __syncthreads();
#pragma unroll
        for (int r = 0; r < 2; ++r) {
            float4 va = *reinterpret_cast<const float4*>(base + (qr + lrow) * ND + kt + lcol + r * 4);
            sA[lrow * 66 + lcol + r * 4 + 0] = va.x;
            sA[lrow * 66 + lcol + r * 4 + 1] = va.y;
            sA[lrow * 66 + lcol + r * 4 + 2] = va.z;
            sA[lrow * 66 + lcol + r * 4 + 3] = va.w;
            float4 vb = *reinterpret_cast<const float4*>(base + (qc + lrow) * ND + kt + lcol + r * 4);
            sB[lrow * 66 + lcol + r * 4 + 0] = vb.x;
            sB[lrow * 66 + lcol + r * 4 + 1] = vb.y;
            sB[lrow * 66 + lcol + r * 4 + 2] = vb.z;
            sB[lrow * 66 + lcol + r * 4 + 3] = vb.w;
        }
        __syncthreads();
#pragma unroll 8
        for (int k = 0; k < 64; ++k) {
            float a0 = sA[r0 * 66 + k], a1 = sA[(r0 + 1) * 66 + k];
            float b0 = sB[c0 * 66 + k], b1 = sB[(c0 + 1) * 66 + k];
            c00 = fmaf(a0, b0, c00);
            c01 = fmaf(a0, b1, c01);
            c10 = fmaf(a1, b0, c10);
            c11 = fmaf(a1, b1, c11);
        }
    }
    float* Gp = g_G + (size_t)j * NL * NL;
    Gp[(qr + r0) * NL + qc + c0] = c00;
    Gp[(qr + r0) * NL + qc + c0 + 1] = c01;
    Gp[(qr + r0 + 1) * NL + qc + c0] = c10;
    Gp[(qr + r0 + 1) * NL + qc + c0 + 1] = c11;

    if (quad == 0) {
        int q = tid >> 2;
        int p = tid & 3;
        const float* sp = sent + (size_t)j * NL * ND + q * ND + p * 128;
        float s = 0.f;
#pragma unroll 8
        for (int t2 = 0; t2 < 32; t2++) {
            float4 v = *reinterpret_cast<const float4*>(sp + t2 * 4);
            s = fmaf(v.x, v.x, fmaf(v.y, v.y, fmaf(v.z, v.z, fmaf(v.w, v.w, s))));
        }
        s += __shfl_xor_sync(0xffffffffu, s, 1);
        s += __shfl_xor_sync(0xffffffffu, s, 2);
        if (p == 0) g_w1[j * NL + q] = sqrtf(s);
    }
}

// ===========================================================================
// Kernel C: pair epilogue (R14 body)
// ===========================================================================
#define P_AH 0
#define P_A2H 4352
#define P_A2L 6656
#define P_GBH 8960
#define P_GBL 11264
#define P_PB 13568
#define P_CM 14656
#define P_CZ 14720
#define P_ES 14784
#define PAIR_SMEM (14848 * 4)

__global__ __launch_bounds__(256) void pair_kernel(float* __restrict__ out) {
    extern __shared__ float shf[];
    uint32_t* shw = reinterpret_cast<uint32_t*>(shf);
    const unsigned FULL = 0xffffffffu;

    const int i = blockIdx.x, j = blockIdx.y;
    const int tid = threadIdx.x;
    const int wid = tid >> 5, lane = tid & 31;
    const int tx = tid & 15, ty = tid >> 4;
    const int row0 = ty * 4, col0 = tx * 4;

    const int gg8 = (col0 >> 4) * 8;
    const int pp = col0 & 15;
    const int wsel = (pp < 8) ? pp : pp - 7;

    float c[4][4];
    const float* Sp = g_S + ((size_t)i * 64) * 4096u + (size_t)j * 64;
#pragma unroll
    for (int m = 0; m < 4; m++) {
        float4 v4 = *reinterpret_cast<const float4*>(Sp + (size_t)(row0 + m) * 4096u + col0);
        c[m][0] = v4.x; c[m][1] = v4.y; c[m][2] = v4.z; c[m][3] = v4.w;
    }

    {
        const float* Gp = g_G + (size_t)j * NL * NL;
        const int f = tx * 4;
        const int fg8 = (f >> 4) * 8;
        const int fp = f & 15;
        const int fw = (fp < 8) ? fp : fp - 7;
#pragma unroll
        for (int r = 0; r < 4; ++r) {
            int q = ty + r * 16;
            float4 gq = *reinterpret_cast<const float4*>(Gp + q * NL + f);
            __half h0 = __float2half_rn(gq.x), h1 = __float2half_rn(gq.y);
            __half h2 = __float2half_rn(gq.z), h3 = __float2half_rn(gq.w);
            __half l0 = __float2half_rn(gq.x - __half2float(h0));
            __half l1 = __float2half_rn(gq.y - __half2float(h1));
            __half l2 = __float2half_rn(gq.z - __half2float(h2));
            __half l3 = __float2half_rn(gq.w - __half2float(h3));
            int wb = q * 36 + fg8 + fw;
            shw[P_GBH + wb] = pkh(h0, h1);
            shw[P_GBH + wb + 2] = pkh(h2, h3);
            shw[P_GBL + wb] = pkh(l0, l1);
            shw[P_GBL + wb + 2] = pkh(l2, l3);
        }
    }

    // ---- col max ----
    {
        float pm[4];
#pragma unroll
        for (int n = 0; n < 4; n++) {
            pm[n] = c[0][n];
#pragma unroll
            for (int m = 1; m < 4; m++) pm[n] = fmaxf(pm[n], c[m][n]);
            pm[n] = fmaxf(pm[n], __shfl_xor_sync(FULL, pm[n], 16));
        }
        if (lane < 16) {
#pragma unroll
            for (int n = 0; n < 4; n++) shf[P_PB + wid * 68 + col0 + n] = pm[n];
        }
    }
    __syncthreads();
    if (tid < 64) {
        float m = -1e30f;
#pragma unroll
        for (int p = 0; p < 8; p++) m = fmaxf(m, shf[P_PB + p * 68 + tid]);
        shf[P_CM + tid] = m;
    }
    __syncthreads();

    // ---- e1 once; col sums ----
    float v[4][4];
    {
        float ps[4];
#pragma unroll
        for (int n = 0; n < 4; n++) {
            float cm = shf[P_CM + col0 + n];
            float s = 0.f;
#pragma unroll
            for (int m = 0; m < 4; m++) {
                float e = fexp(c[m][n] - cm);
                v[m][n] = e;
                s += e;
            }
            ps[n] = s + __shfl_xor_sync(FULL, s, 16);
        }
        if (lane < 16) {
#pragma unroll
            for (int n = 0; n < 4; n++) shf[P_PB + wid * 68 + col0 + n] = ps[n];
        }
    }
    __syncthreads();
    if (tid < 64) {
        float z = 0.f;
#pragma unroll
        for (int p = 0; p < 8; p++) z += shf[P_PB + p * 68 + tid];
        shf[P_CZ + tid] = 4.f / z;
    }
    __syncthreads();

#pragma unroll
    for (int n = 0; n < 4; n++) {
        float zr = shf[P_CZ + col0 + n];
#pragma unroll
        for (int m = 0; m < 4; m++) v[m][n] *= zr;
    }

    float rm[4];
#pragma unroll
    for (int m = 0; m < 4; m++) {
        float pm = v[m][0];
#pragma unroll
        for (int n = 1; n < 4; n++) pm = fmaxf(pm, v[m][n]);
#pragma unroll
        for (int off = 1; off < 16; off <<= 1)
            pm = fmaxf(pm, __shfl_xor_sync(FULL, pm, off));
        rm[m] = pm;
    }

    float rz[4];
#pragma unroll
    for (int m = 0; m < 4; m++) {
        float s = 0.f;
#pragma unroll
        for (int n = 0; n < 4; n++) {
            float e = fexp(v[m][n] - rm[m]);
            v[m][n] = e;
            s += e;
        }
#pragma unroll
        for (int off = 1; off < 16; off <<= 1)
            s += __shfl_xor_sync(FULL, s, off);
        rz[m] = 1.f / s;
    }

#pragma unroll
    for (int m = 0; m < 4; m++) {
        float w12p = 0.f;
        float a2v[4];
#pragma unroll
        for (int n = 0; n < 4; n++) {
            float a2 = v[m][n] * rz[m];
            a2v[n] = a2;
            v[m][n] = a2;
            w12p = fmaf(a2, c[m][n], w12p);
            shf[P_AH + (row0 + m) * 68 + col0 + n] = a2;
        }
#pragma unroll
        for (int off = 1; off < 16; off <<= 1)
            w12p += __shfl_xor_sync(FULL, w12p, off);
        if (tx == 0) shf[P_CM + row0 + m] = w12p;
        __half h0 = __float2half_rn(a2v[0]), h1 = __float2half_rn(a2v[1]);
        __half h2 = __float2half_rn(a2v[2]), h3 = __float2half_rn(a2v[3]);
        __half l0 = __float2half_rn(a2v[0] - __half2float(h0));
        __half l1 = __float2half_rn(a2v[1] - __half2float(h1));
        __half l2 = __float2half_rn(a2v[2] - __half2float(h2));
        __half l3 = __float2half_rn(a2v[3] - __half2float(h3));
        int wb = (row0 + m) * 36 + gg8 + wsel;
        shw[P_A2H + wb] = pkh(h0, h1);
        shw[P_A2H + wb + 2] = pkh(h2, h3);
        shw[P_A2L + wb] = pkh(l0, l1);
        shw[P_A2L + wb + 2] = pkh(l2, l3);
    }
    __syncthreads();

    // ---- GEMM2 on tensor ----
    const uint32_t warpM2 = (uint32_t)(wid & 1) * 32u;
    const uint32_t warpN2 = (uint32_t)(wid >> 1) * 16u;
    const uint32_t lg = lane >> 2, lt = lane & 3;
    const uint32_t a2hB = smem_u32(shw + P_A2H);
    const uint32_t a2lB = smem_u32(shw + P_A2L);
    const uint32_t gbhB = smem_u32(shw + P_GBH);
    const uint32_t gblB = smem_u32(shw + P_GBL);

    float t4[2][2][4];
#pragma unroll
    for (int mi = 0; mi < 2; ++mi)
#pragma unroll
        for (int ni = 0; ni < 2; ++ni)
#pragma unroll
            for (int r = 0; r < 4; ++r) t4[mi][ni][r] = 0.f;

#pragma unroll
    for (int kk = 0; kk < 4; ++kk) {
        const uint32_t kw = (uint32_t)kk * 8u + 2u * lt;
        uint32_t bh[2][2], bl[2][2];
#pragma unroll
        for (int ni = 0; ni < 2; ++ni) {
            uint32_t r0 = (warpN2 + ni * 8u + lg) * 36u + kw;
            lds64(bh[ni][0], bh[ni][1], gbhB + r0 * 4u);
            lds64(bl[ni][0], bl[ni][1], gblB + r0 * 4u);
        }
#pragma unroll
        for (int mi = 0; mi < 2; ++mi) {
            uint32_t ah[4], al[4];
            uint32_t r0 = (warpM2 + mi * 16u + lg) * 36u + kw;
            uint32_t r1 = r0 + 8u * 36u;
            lds64(ah[0], ah[2], a2hB + r0 * 4u);
            lds64(ah[1], ah[3], a2hB + r1 * 4u);
            lds64(al[0], al[2], a2lB + r0 * 4u);
            lds64(al[1], al[3], a2lB + r1 * 4u);
#pragma unroll
            for (int ni = 0; ni < 2; ++ni) {
                mma_f16(t4[mi][ni], ah, bh[ni]);
                mma_f16(t4[mi][ni], ah, bl[ni]);
                mma_f16(t4[mi][ni], al, bh[ni]);
            }
        }
    }

    {
        float pr[2][2];
#pragma unroll
        for (int mi = 0; mi < 2; ++mi) { pr[mi][0] = 0.f; pr[mi][1] = 0.f; }
#pragma unroll
        for (int mi = 0; mi < 2; ++mi)
#pragma unroll
            for (int ni = 0; ni < 2; ++ni) {
                int cc = warpN2 + ni * 8 + lt * 2;
                int r0 = warpM2 + mi * 16 + lg;
                int r1 = r0 + 8;
                pr[mi][0] = fmaf(t4[mi][ni][0], shf[P_AH + r0 * 68 + cc],
                             fmaf(t4[mi][ni][1], shf[P_AH + r0 * 68 + cc + 1], pr[mi][0]));
                pr[mi][1] = fmaf(t4[mi][ni][2], shf[P_AH + r1 * 68 + cc],
                             fmaf(t4[mi][ni][3], shf[P_AH + r1 * 68 + cc + 1], pr[mi][1]));
            }
#pragma unroll
        for (int mi = 0; mi < 2; ++mi)
#pragma unroll
            for (int rr = 0; rr < 2; ++rr) {
                pr[mi][rr] += __shfl_xor_sync(FULL, pr[mi][rr], 1);
                pr[mi][rr] += __shfl_xor_sync(FULL, pr[mi][rr], 2);
            }
        if (lt == 0) {
            int cg = wid >> 1;
#pragma unroll
            for (int mi = 0; mi < 2; ++mi) {
                int r0 = warpM2 + mi * 16 + lg;
                shf[P_PB + cg * 64 + r0] = pr[mi][0];
                shf[P_PB + cg * 64 + r0 + 8] = pr[mi][1];
            }
        }
    }
    __syncthreads();

    if (tid < 64) {
        float w2sq = shf[P_PB + tid] + shf[P_PB + 64 + tid] +
                     shf[P_PB + 128 + tid] + shf[P_PB + 192 + tid];
        float w2 = sqrtf(fmaxf(w2sq, 0.f));
        float den = fmaxf(g_w1[i * NL + tid] * w2, 1e-8f);
        float cs = shf[P_CM + tid] / den;
        shf[P_ES + tid] = __expf(5.f * cs);
    }
    __syncthreads();
    if (tid == 0) {
        float z = 0.f;
#pragma unroll
        for (int q = 0; q < 64; q++) z += shf[P_ES + q];
        g_sim[j * NB + i] = 10.f * logf(z);
    }

    if (i == j) {
        float* ap = out + 1 + (size_t)i * NL * NL;
#pragma unroll
        for (int m = 0; m < 4; m++)
#pragma unroll
            for (int n = 0; n < 4; n++)
                ap[(row0 + m) * NL + col0 + n] = shf[P_AH + (row0 + m) * 68 + col0 + n];
    }
}

// ===========================================================================
// loss
// ===========================================================================
__global__ __launch_bounds__(256) void loss_kernel(float* __restrict__ out) {
    __shared__ float sm[64 * 64];
    __shared__ float sh[64];
    const int tid = threadIdx.x;
#pragma unroll
    for (int r = 0; r < 4; ++r) {
        int idx = tid * 4 + r * 1024;
        *reinterpret_cast<float4*>(sm + idx) = *reinterpret_cast<const float4*>(g_sim + idx);
    }
    __syncthreads();
    if (tid < 64) {
        int t = tid;
        float m1 = -1e30f, m2 = -1e30f;
#pragma unroll 8
        for (int b = 0; b < NB; b++) {
            m1 = fmaxf(m1, sm[t * NB + b]);
            m2 = fmaxf(m2, sm[b * NB + t]);
        }
        float z1 = 0.f, z2 = 0.f;
#pragma unroll 8
        for (int b = 0; b < NB; b++) {
            z1 += fexp(sm[t * NB + b] - m1);
            z2 += fexp(sm[b * NB + t] - m2);
        }
        float dg = sm[t * NB + t];
        sh[t] = (dg - (m1 + logf(z1))) + (dg - (m2 + logf(z2)));
    }
    __syncthreads();
    if (tid == 0) {
        float s = 0.f;
#pragma unroll
        for (int q = 0; q < NB; q++) s += sh[q];
        out[0] = -s / (2.f * (float)NB);
    }
}

extern "C" void kernel_launch(void* const* d_in, const int* in_sizes, int n_in,
                              void* d_out, int out_size) {
    const float* ecg = (const float*)d_in[0];
    const float* sent = (const float*)d_in[1];
    float* out = (float*)d_out;

    cudaFuncSetAttribute(s_gemm_kernel, cudaFuncAttributeMaxDynamicSharedMemorySize, SMEM_TOTAL);
    cudaFuncSetAttribute(pair_kernel, cudaFuncAttributeMaxDynamicSharedMemorySize, PAIR_SMEM);

    s_gemm_kernel<<<dim3(32, 32), 256, SMEM_TOTAL>>>(ecg, sent);
    gram_kernel<<<256, 256>>>(ecg, sent);
    pair_kernel<<<dim3(64, 64), 256, PAIR_SMEM>>>(out);
    loss_kernel<<<1, 256>>>(out);
}